// round 4
// baseline (speedup 1.0000x reference)
#include <cuda_runtime.h>

// Problem shape (fixed per reference): x (64,512,1024) f32, W (512,512), b (512),
// gamma (1), beta (1).  out[b,u,f] = x[b,u,f] + relu(scale * sum_t W[u,t]*x[b,t,f] + cbias[u])
// with scale = gamma*rsqrt(var+eps), cbias[u] = b[u] + (beta - scale*mean)*rowsumW[u].

#define B_DIM 64
#define T_DIM 512
#define F_DIM 1024
#define NELEM (B_DIM * T_DIM * F_DIM)   // 33554432
#define NF4   (NELEM / 4)               // 8388608
#define P_BLOCKS 2048
#define EPSV 1e-5f

// Scratch (device globals — no allocation allowed)
__device__ float g_psum[P_BLOCKS];
__device__ float g_psq[P_BLOCKS];
__device__ float g_scale;
__device__ float g_cbias[T_DIM];

// ---------------------------------------------------------------------------
// Kernel 1: per-block partial sum / sum-of-squares over all of x
// ---------------------------------------------------------------------------
__global__ __launch_bounds__(256) void stats_partial(const float4* __restrict__ x) {
    const int tid = threadIdx.x;
    const int base = blockIdx.x * 4096;  // 4096 float4 per block, 16 per thread
    float s = 0.f, q = 0.f;
#pragma unroll
    for (int i = 0; i < 16; ++i) {
        float4 v = x[base + i * 256 + tid];
        s += v.x + v.y + v.z + v.w;
        q += v.x * v.x + v.y * v.y + v.z * v.z + v.w * v.w;
    }
#pragma unroll
    for (int o = 16; o > 0; o >>= 1) {
        s += __shfl_xor_sync(0xffffffffu, s, o);
        q += __shfl_xor_sync(0xffffffffu, q, o);
    }
    __shared__ float ws[8], wq[8];
    if ((tid & 31) == 0) { ws[tid >> 5] = s; wq[tid >> 5] = q; }
    __syncthreads();
    if (tid == 0) {
        float S = 0.f, Q = 0.f;
#pragma unroll
        for (int i = 0; i < 8; ++i) { S += ws[i]; Q += wq[i]; }
        g_psum[blockIdx.x] = S;
        g_psq[blockIdx.x]  = Q;
    }
}

// ---------------------------------------------------------------------------
// Kernel 2: finalize stats, compute scale and per-row combined bias
// ---------------------------------------------------------------------------
__global__ __launch_bounds__(512) void stats_finalize(const float* __restrict__ W,
                                                      const float* __restrict__ bias,
                                                      const float* __restrict__ gamma,
                                                      const float* __restrict__ beta) {
    __shared__ double ds[512], dq[512];
    __shared__ float sh_shift;
    const int tid = threadIdx.x;

    double s = 0.0, q = 0.0;
#pragma unroll
    for (int j = 0; j < P_BLOCKS / 512; ++j) {
        s += (double)g_psum[tid + j * 512];
        q += (double)g_psq[tid + j * 512];
    }
    ds[tid] = s; dq[tid] = q;
    __syncthreads();
#pragma unroll
    for (int o = 256; o > 0; o >>= 1) {
        if (tid < o) { ds[tid] += ds[tid + o]; dq[tid] += dq[tid + o]; }
        __syncthreads();
    }
    if (tid == 0) {
        double mean = ds[0] / (double)NELEM;
        double var  = dq[0] / (double)NELEM - mean * mean;
        float inv   = 1.0f / sqrtf((float)var + EPSV);
        float sc    = gamma[0] * inv;
        g_scale  = sc;
        sh_shift = beta[0] - sc * (float)mean;
    }
    __syncthreads();

    // Per-row W sums -> combined bias. One row per thread.
    const float* wr = W + tid * T_DIM;
    float rs = 0.f;
#pragma unroll 8
    for (int t = 0; t < T_DIM; ++t) rs += wr[t];
    g_cbias[tid] = bias[tid] + sh_shift * rs;
}

// ---------------------------------------------------------------------------
// Kernel 3: fused batched GEMM (128x128x8 tiles, 8x8 per thread) + epilogue
//   C[b,u,f] = x[b,u,f] + relu(scale * sum_t W[u,t] * x[b,t,f] + cbias[u])
// ---------------------------------------------------------------------------
#define BM 128
#define BN 128
#define BK 8

__global__ __launch_bounds__(256, 2) void gemm_fused(const float* __restrict__ x,
                                                     const float* __restrict__ W,
                                                     float* __restrict__ out) {
    __shared__ __align__(16) float As[BK][BM];  // A transposed: As[k][m]
    __shared__ __align__(16) float Bs[BK][BN];

    const int tid   = threadIdx.x;
    const int batch = blockIdx.z;
    const int m0    = blockIdx.y * BM;  // u tile
    const int n0    = blockIdx.x * BN;  // f tile
    const float* xb = x + (size_t)batch * T_DIM * F_DIM;

    const int tx = tid & 15;   // n micro
    const int ty = tid >> 4;   // m micro

    // Global load mapping
    const int arow = tid >> 1;            // 0..127
    const int kh   = (tid & 1) * 4;       // 0 or 4
    const float* aptr = W + (size_t)(m0 + arow) * T_DIM + kh;
    const int brow = tid >> 5;            // 0..7
    const int bcol = (tid & 31) * 4;      // 0..124
    const float* bptr = xb + (size_t)brow * F_DIM + n0 + bcol;

    float acc[2][2][4][4];
#pragma unroll
    for (int a = 0; a < 2; ++a)
#pragma unroll
        for (int b = 0; b < 2; ++b)
#pragma unroll
            for (int i = 0; i < 4; ++i)
#pragma unroll
                for (int j = 0; j < 4; ++j) acc[a][b][i][j] = 0.f;

    float4 wreg = *(const float4*)(aptr);
    float4 xreg = *(const float4*)(bptr);

    const int NKT = T_DIM / BK;  // 64
    for (int kt = 0; kt < NKT; ++kt) {
        As[kh + 0][arow] = wreg.x;
        As[kh + 1][arow] = wreg.y;
        As[kh + 2][arow] = wreg.z;
        As[kh + 3][arow] = wreg.w;
        *(float4*)&Bs[brow][bcol] = xreg;
        __syncthreads();

        if (kt + 1 < NKT) {  // prefetch next tile into registers (overlaps compute)
            wreg = *(const float4*)(aptr + (kt + 1) * BK);
            xreg = *(const float4*)(bptr + (size_t)(kt + 1) * BK * F_DIM);
        }

#pragma unroll
        for (int k = 0; k < BK; ++k) {
            float4 a0 = *(const float4*)&As[k][ty * 4];
            float4 a1 = *(const float4*)&As[k][64 + ty * 4];
            float4 b0 = *(const float4*)&Bs[k][tx * 4];
            float4 b1 = *(const float4*)&Bs[k][64 + tx * 4];
            float av[2][4] = {{a0.x, a0.y, a0.z, a0.w}, {a1.x, a1.y, a1.z, a1.w}};
            float bv[2][4] = {{b0.x, b0.y, b0.z, b0.w}, {b1.x, b1.y, b1.z, b1.w}};
#pragma unroll
            for (int mq = 0; mq < 2; ++mq)
#pragma unroll
                for (int i = 0; i < 4; ++i)
#pragma unroll
                    for (int nq = 0; nq < 2; ++nq)
#pragma unroll
                        for (int j = 0; j < 4; ++j)
                            acc[mq][nq][i][j] = fmaf(av[mq][i], bv[nq][j], acc[mq][nq][i][j]);
        }
        __syncthreads();
    }

    // Epilogue: scale, bias, relu, residual
    const float sc = g_scale;
    float* ob = out + (size_t)batch * T_DIM * F_DIM;
#pragma unroll
    for (int mq = 0; mq < 2; ++mq) {
#pragma unroll
        for (int i = 0; i < 4; ++i) {
            const int row = m0 + mq * 64 + ty * 4 + i;
            const float cb = g_cbias[row];
            const float* xrow = xb + (size_t)row * F_DIM;
            float* orow = ob + (size_t)row * F_DIM;
#pragma unroll
            for (int nq = 0; nq < 2; ++nq) {
                const int col = n0 + nq * 64 + tx * 4;
                float4 xv = *(const float4*)(xrow + col);
                float4 r;
                r.x = xv.x + fmaxf(fmaf(sc, acc[mq][nq][i][0], cb), 0.f);
                r.y = xv.y + fmaxf(fmaf(sc, acc[mq][nq][i][1], cb), 0.f);
                r.z = xv.z + fmaxf(fmaf(sc, acc[mq][nq][i][2], cb), 0.f);
                r.w = xv.w + fmaxf(fmaf(sc, acc[mq][nq][i][3], cb), 0.f);
                *(float4*)(orow + col) = r;
            }
        }
    }
}

// ---------------------------------------------------------------------------
extern "C" void kernel_launch(void* const* d_in, const int* in_sizes, int n_in,
                              void* d_out, int out_size) {
    const float* x     = (const float*)d_in[0];
    const float* W     = (const float*)d_in[1];
    const float* bias  = (const float*)d_in[2];
    const float* gamma = (const float*)d_in[3];
    const float* beta  = (const float*)d_in[4];
    float* out = (float*)d_out;

    stats_partial<<<P_BLOCKS, 256>>>((const float4*)x);
    stats_finalize<<<1, 512>>>(W, bias, gamma, beta);

    dim3 grid(F_DIM / BN, T_DIM / BM, B_DIM);  // (8, 4, 64)
    gemm_fused<<<grid, 256>>>(x, W, out);
}

// round 10
// speedup vs baseline: 1.3193x; 1.3193x over previous
#include <cuda_runtime.h>
#include <cuda_bf16.h>
#include <cstdint>

// out[b,u,f] = x[b,u,f] + relu(scale * sum_t W[u,t]*x[b,t,f] + cbias[u])
//   scale = gamma*rsqrt(var+eps), cbias[u] = b[u] + (beta - scale*mean)*rowsumW[u]
// GEMM on tensor cores (mma.sync bf16) via hi/lo split: W@x ~= Whi@xhi + Wlo@xhi + Whi@xlo

#define B_DIM 64
#define T_DIM 512
#define F_DIM 1024
#define NELEM (B_DIM * T_DIM * F_DIM)
#define EPSV 1e-5f
#define PBLK 32768

// ----- device scratch (no allocation allowed) -----
__device__ __nv_bfloat16 g_xhiT[(size_t)B_DIM * F_DIM * T_DIM];  // [b, f, t]
__device__ __nv_bfloat16 g_xloT[(size_t)B_DIM * F_DIM * T_DIM];
__device__ __nv_bfloat16 g_whi[T_DIM * T_DIM];                   // [u, t]
__device__ __nv_bfloat16 g_wlo[T_DIM * T_DIM];
__device__ float g_psum[PBLK];
__device__ float g_psq[PBLK];
__device__ float g_scale;
__device__ float g_cbias[T_DIM];

// ---------------------------------------------------------------------------
// Kernel 1: split x into bf16 hi/lo, TRANSPOSED to [b, f, t]; fused stats.
// ---------------------------------------------------------------------------
__global__ __launch_bounds__(256) void convert_x(const float* __restrict__ x) {
    __shared__ __nv_bfloat16 hs[32][33];
    __shared__ __nv_bfloat16 ls[32][33];
    const int tx = threadIdx.x, ty = threadIdx.y;   // (32, 8)
    const int f0 = blockIdx.x * 32, t0 = blockIdx.y * 32, b = blockIdx.z;
    const float* xb = x + (size_t)b * T_DIM * F_DIM;

    float s = 0.f, q = 0.f;
#pragma unroll
    for (int j = 0; j < 4; ++j) {
        float v = xb[(size_t)(t0 + ty + 8 * j) * F_DIM + f0 + tx];
        s += v; q += v * v;
        __nv_bfloat16 h = __float2bfloat16_rn(v);
        hs[ty + 8 * j][tx] = h;
        ls[ty + 8 * j][tx] = __float2bfloat16_rn(v - __bfloat162float(h));
    }
    __syncthreads();
    const size_t ob = ((size_t)b * F_DIM + f0) * T_DIM + t0;
#pragma unroll
    for (int j = 0; j < 4; ++j) {
        size_t o = ob + (size_t)(ty + 8 * j) * T_DIM + tx;
        g_xhiT[o] = hs[tx][ty + 8 * j];
        g_xloT[o] = ls[tx][ty + 8 * j];
    }
    const int tid = ty * 32 + tx;
#pragma unroll
    for (int o = 16; o > 0; o >>= 1) {
        s += __shfl_xor_sync(0xffffffffu, s, o);
        q += __shfl_xor_sync(0xffffffffu, q, o);
    }
    __shared__ float ws[8], wq[8];
    if ((tid & 31) == 0) { ws[tid >> 5] = s; wq[tid >> 5] = q; }
    __syncthreads();
    if (tid == 0) {
        float S = 0.f, Q = 0.f;
#pragma unroll
        for (int i = 0; i < 8; ++i) { S += ws[i]; Q += wq[i]; }
        int bid = (blockIdx.z * gridDim.y + blockIdx.y) * gridDim.x + blockIdx.x;
        g_psum[bid] = S; g_psq[bid] = Q;
    }
}

// ---------------------------------------------------------------------------
// Kernel 2: split W into bf16 hi/lo ([u, t], t contiguous)
// ---------------------------------------------------------------------------
__global__ __launch_bounds__(512) void convert_w(const float* __restrict__ W) {
    int i = blockIdx.x * 512 + threadIdx.x;
    float v = W[i];
    __nv_bfloat16 h = __float2bfloat16_rn(v);
    g_whi[i] = h;
    g_wlo[i] = __float2bfloat16_rn(v - __bfloat162float(h));
}

// ---------------------------------------------------------------------------
// Kernel 3: finalize stats -> scale, per-row combined bias
// ---------------------------------------------------------------------------
__global__ __launch_bounds__(512) void stats_finalize(const float* __restrict__ W,
                                                      const float* __restrict__ bias,
                                                      const float* __restrict__ gamma,
                                                      const float* __restrict__ beta) {
    __shared__ double ds[512], dq[512];
    __shared__ float sh_shift;
    const int tid = threadIdx.x;
    double s = 0.0, q = 0.0;
#pragma unroll 4
    for (int j = 0; j < PBLK / 512; ++j) {
        s += (double)g_psum[tid + j * 512];
        q += (double)g_psq[tid + j * 512];
    }
    ds[tid] = s; dq[tid] = q;
    __syncthreads();
#pragma unroll
    for (int o = 256; o > 0; o >>= 1) {
        if (tid < o) { ds[tid] += ds[tid + o]; dq[tid] += dq[tid + o]; }
        __syncthreads();
    }
    if (tid == 0) {
        double mean = ds[0] / (double)NELEM;
        double var  = dq[0] / (double)NELEM - mean * mean;
        float inv = 1.0f / sqrtf((float)var + EPSV);
        float sc  = gamma[0] * inv;
        g_scale  = sc;
        sh_shift = beta[0] - sc * (float)mean;
    }
    __syncthreads();
    const float* wr = W + tid * T_DIM;
    float rs = 0.f;
#pragma unroll 8
    for (int t = 0; t < T_DIM; ++t) rs += wr[t];
    g_cbias[tid] = bias[tid] + sh_shift * rs;
}

// ---------------------------------------------------------------------------
// Kernel 4: mma.sync bf16 GEMM. CTA tile 128(M=u) x 128(N=f), BK=32, 3 stages.
// SMEM row layout per tile row: [hi 64B | lo 64B] = 128B, XOR-swizzled.
// ---------------------------------------------------------------------------
#define GM 128
#define GN 128
#define BK 32
#define NIT (T_DIM / BK)       // 16
#define STG 32768              // 16KB A + 16KB B per stage
#define NSTAGE 3
#define SM_DYN (NSTAGE * STG)  // 98304

static __device__ __forceinline__ uint32_t smem_u32(const void* p) {
    uint32_t a;
    asm("{ .reg .u64 t; cvta.to.shared.u64 t, %1; cvt.u32.u64 %0, t; }" : "=r"(a) : "l"(p));
    return a;
}
static __device__ __forceinline__ void cpa16(uint32_t s, const void* g) {
    asm volatile("cp.async.cg.shared.global [%0], [%1], 16;" :: "r"(s), "l"(g));
}
static __device__ __forceinline__ void cpa_commit() {
    asm volatile("cp.async.commit_group;" ::: "memory");
}
template <int N> static __device__ __forceinline__ void cpa_wait() {
    asm volatile("cp.async.wait_group %0;" :: "n"(N) : "memory");
}
static __device__ __forceinline__ void ldmx4(uint32_t* r, uint32_t a) {
    asm volatile("ldmatrix.sync.aligned.m8n8.x4.shared.b16 {%0,%1,%2,%3}, [%4];"
        : "=r"(r[0]), "=r"(r[1]), "=r"(r[2]), "=r"(r[3]) : "r"(a));
}
static __device__ __forceinline__ void mma16816(float* d, const uint32_t* a,
                                                uint32_t b0, uint32_t b1) {
    asm volatile("mma.sync.aligned.m16n8k16.row.col.f32.bf16.bf16.f32 "
        "{%0,%1,%2,%3}, {%4,%5,%6,%7}, {%8,%9}, {%0,%1,%2,%3};"
        : "+f"(d[0]), "+f"(d[1]), "+f"(d[2]), "+f"(d[3])
        : "r"(a[0]), "r"(a[1]), "r"(a[2]), "r"(a[3]), "r"(b0), "r"(b1));
}

// chunks: 1024 for A (128 rows x 8x16B), 1024 for B. 256 threads -> 4+4 each.
static __device__ __forceinline__ void load_stage(uint32_t sb, int m0, size_t bbase,
                                                  int k0, int tid) {
#pragma unroll
    for (int i = 0; i < 4; ++i) {
        int idx = tid + i * 256;
        int row = idx >> 3, c = idx & 7;
        uint32_t sw = (uint32_t)(row * 128) + (((uint32_t)(c * 16)) ^ ((row & 7) << 4));
        const __nv_bfloat16* src = (c < 4)
            ? (g_whi + (size_t)(m0 + row) * T_DIM + k0 + c * 8)
            : (g_wlo + (size_t)(m0 + row) * T_DIM + k0 + (c - 4) * 8);
        cpa16(sb + sw, src);
    }
#pragma unroll
    for (int i = 0; i < 4; ++i) {
        int idx = tid + i * 256;
        int row = idx >> 3, c = idx & 7;
        uint32_t sw = (uint32_t)(row * 128) + (((uint32_t)(c * 16)) ^ ((row & 7) << 4));
        const __nv_bfloat16* src = (c < 4)
            ? (g_xhiT + bbase + (size_t)row * T_DIM + k0 + c * 8)
            : (g_xloT + bbase + (size_t)row * T_DIM + k0 + (c - 4) * 8);
        cpa16(sb + 16384 + sw, src);
    }
}

__global__ __launch_bounds__(256, 1) void gemm_tc(const float* __restrict__ x,
                                                  float* __restrict__ out) {
    extern __shared__ __align__(16) char smem[];
    const uint32_t sbase = smem_u32(smem);
    const int tid = threadIdx.x;
    const int n0 = blockIdx.x * GN;
    const int m0 = blockIdx.y * GM;
    const int b  = blockIdx.z;
    const size_t bbase = ((size_t)b * F_DIM + n0) * T_DIM;

    const int lane = tid & 31, w = tid >> 5;
    const int wm = w & 3;        // 0..3 -> 32-row m slice
    const int wn = w >> 2;       // 0..1 -> 64-col n slice
    const uint32_t X = (uint32_t)(((lane >> 4) ^ (lane & 7)) << 4);
    const uint32_t PA0 = (uint32_t)((wm * 32 + (lane & 15)) * 128);
    const uint32_t PA1 = PA0 + 16 * 128;
    uint32_t PB[4];
#pragma unroll
    for (int g = 0; g < 4; ++g)
        PB[g] = 16384u + (uint32_t)((wn * 64 + g * 16 + (lane & 15)) * 128);

    float acc[2][8][4];
#pragma unroll
    for (int mi = 0; mi < 2; ++mi)
#pragma unroll
        for (int nj = 0; nj < 8; ++nj)
#pragma unroll
            for (int e = 0; e < 4; ++e) acc[mi][nj][e] = 0.f;

    // prologue: stages 0, 1
    load_stage(sbase, m0, bbase, 0, tid);
    cpa_commit();
    load_stage(sbase + STG, m0, bbase, BK, tid);
    cpa_commit();

    int stage = 0;
#pragma unroll 1
    for (int it = 0; it < NIT; ++it) {
        if (it + 2 >= NIT) cpa_wait<0>(); else cpa_wait<1>();
        __syncthreads();
        if (it + 2 < NIT) {
            int ns = stage + 2; if (ns >= NSTAGE) ns -= NSTAGE;
            load_stage(sbase + ns * STG, m0, bbase, (it + 2) * BK, tid);
            cpa_commit();
        }
        const uint32_t sb = sbase + stage * STG;
        const uint32_t sA0 = sb + PA0, sA1 = sb + PA1;

#pragma unroll
        for (int kk = 0; kk < 2; ++kk) {
            const uint32_t ch = (uint32_t)(kk * 32);       // hi bytes
            const uint32_t cl = ch + 64u;                  // lo bytes
            uint32_t ah[2][4], al[2][4];
            ldmx4(ah[0], sA0 + (ch ^ X));
            ldmx4(al[0], sA0 + (cl ^ X));
            ldmx4(ah[1], sA1 + (ch ^ X));
            ldmx4(al[1], sA1 + (cl ^ X));
#pragma unroll
            for (int g = 0; g < 4; ++g) {
                uint32_t bh[4], bl[4];
                ldmx4(bh, sb + PB[g] + (ch ^ X));
                ldmx4(bl, sb + PB[g] + (cl ^ X));
#pragma unroll
                for (int mi = 0; mi < 2; ++mi) {
                    // n-subtile 2g   : regs {0,2};  2g+1: regs {1,3}
                    mma16816(acc[mi][2 * g],     ah[mi], bh[0], bh[2]);
                    mma16816(acc[mi][2 * g],     al[mi], bh[0], bh[2]);
                    mma16816(acc[mi][2 * g],     ah[mi], bl[0], bl[2]);
                    mma16816(acc[mi][2 * g + 1], ah[mi], bh[1], bh[3]);
                    mma16816(acc[mi][2 * g + 1], al[mi], bh[1], bh[3]);
                    mma16816(acc[mi][2 * g + 1], ah[mi], bl[1], bl[3]);
                }
            }
        }
        ++stage; if (stage == NSTAGE) stage = 0;
    }

    // ---- epilogue: out = x + relu(sc*acc + cbias[row]) ----
    const float sc = g_scale;
    const int rbase = m0 + wm * 32 + (lane >> 2);
    const int cbase = n0 + wn * 64 + (lane & 3) * 2;
#pragma unroll
    for (int mi = 0; mi < 2; ++mi) {
        const int r0 = rbase + mi * 16;
        const float cb0 = g_cbias[r0];
        const float cb1 = g_cbias[r0 + 8];
        const float* x0 = x + ((size_t)b * T_DIM + r0) * F_DIM;
        float* o0 = out + ((size_t)b * T_DIM + r0) * F_DIM;
#pragma unroll
        for (int nj = 0; nj < 8; ++nj) {
            const int c = cbase + nj * 8;
            float2 xv0 = *(const float2*)(x0 + c);
            float2 xv1 = *(const float2*)(x0 + 8 * F_DIM + c);
            float2 r0v, r1v;
            r0v.x = xv0.x + fmaxf(fmaf(sc, acc[mi][nj][0], cb0), 0.f);
            r0v.y = xv0.y + fmaxf(fmaf(sc, acc[mi][nj][1], cb0), 0.f);
            r1v.x = xv1.x + fmaxf(fmaf(sc, acc[mi][nj][2], cb1), 0.f);
            r1v.y = xv1.y + fmaxf(fmaf(sc, acc[mi][nj][3], cb1), 0.f);
            *(float2*)(o0 + c) = r0v;
            *(float2*)(o0 + 8 * F_DIM + c) = r1v;
        }
    }
}

// ---------------------------------------------------------------------------
extern "C" void kernel_launch(void* const* d_in, const int* in_sizes, int n_in,
                              void* d_out, int out_size) {
    const float* x     = (const float*)d_in[0];
    const float* W     = (const float*)d_in[1];
    const float* bias  = (const float*)d_in[2];
    const float* gamma = (const float*)d_in[3];
    const float* beta  = (const float*)d_in[4];
    float* out = (float*)d_out;

    cudaFuncSetAttribute(gemm_tc, cudaFuncAttributeMaxDynamicSharedMemorySize, SM_DYN);

    dim3 cgrid(F_DIM / 32, T_DIM / 32, B_DIM);      // (32, 16, 64)
    convert_x<<<cgrid, dim3(32, 8)>>>(x);
    convert_w<<<T_DIM * T_DIM / 512, 512>>>(W);
    stats_finalize<<<1, 512>>>(W, bias, gamma, beta);

    dim3 ggrid(F_DIM / GN, T_DIM / GM, B_DIM);      // (8, 4, 64)
    gemm_tc<<<ggrid, 256, SM_DYN>>>(x, out);
}

// round 11
// speedup vs baseline: 1.6845x; 1.2768x over previous
#include <cuda_runtime.h>
#include <cuda_bf16.h>
#include <cstdint>

// out[b,u,f] = x[b,u,f] + relu(scale * sum_t W[u,t]*x[b,t,f] + cbias[u])
//   scale = gamma*rsqrt(var+eps), cbias[u] = b[u] + (beta - scale*mean)*rowsumW[u]
// GEMM on tensor cores (mma.sync bf16) via hi/lo split: W@x ~= Whi@xhi + Wlo@xhi + Whi@xlo

#define B_DIM 64
#define T_DIM 512
#define F_DIM 1024
#define NELEM (B_DIM * T_DIM * F_DIM)
#define EPSV 1e-5f
#define PBLK 32768

// ----- device scratch (no allocation allowed) -----
__device__ __nv_bfloat16 g_xhiT[(size_t)B_DIM * F_DIM * T_DIM];  // [b, f, t]
__device__ __nv_bfloat16 g_xloT[(size_t)B_DIM * F_DIM * T_DIM];
__device__ __nv_bfloat16 g_whi[T_DIM * T_DIM];                   // [u, t]
__device__ __nv_bfloat16 g_wlo[T_DIM * T_DIM];
__device__ float g_wrowsum[T_DIM];
__device__ float g_psum[PBLK];
__device__ float g_psq[PBLK];
__device__ float g_scale;
__device__ float g_cbias[T_DIM];

// ---------------------------------------------------------------------------
// Kernel 1: split x into bf16 hi/lo, TRANSPOSED to [b, f, t]; fused stats.
// ---------------------------------------------------------------------------
__global__ __launch_bounds__(256) void convert_x(const float* __restrict__ x) {
    __shared__ __nv_bfloat16 hs[32][33];
    __shared__ __nv_bfloat16 ls[32][33];
    const int tx = threadIdx.x, ty = threadIdx.y;   // (32, 8)
    const int f0 = blockIdx.x * 32, t0 = blockIdx.y * 32, b = blockIdx.z;
    const float* xb = x + (size_t)b * T_DIM * F_DIM;

    float s = 0.f, q = 0.f;
#pragma unroll
    for (int j = 0; j < 4; ++j) {
        float v = xb[(size_t)(t0 + ty + 8 * j) * F_DIM + f0 + tx];
        s += v; q += v * v;
        __nv_bfloat16 h = __float2bfloat16_rn(v);
        hs[ty + 8 * j][tx] = h;
        ls[ty + 8 * j][tx] = __float2bfloat16_rn(v - __bfloat162float(h));
    }
    __syncthreads();
    const size_t ob = ((size_t)b * F_DIM + f0) * T_DIM + t0;
#pragma unroll
    for (int j = 0; j < 4; ++j) {
        size_t o = ob + (size_t)(ty + 8 * j) * T_DIM + tx;
        g_xhiT[o] = hs[tx][ty + 8 * j];
        g_xloT[o] = ls[tx][ty + 8 * j];
    }
    const int tid = ty * 32 + tx;
#pragma unroll
    for (int o = 16; o > 0; o >>= 1) {
        s += __shfl_xor_sync(0xffffffffu, s, o);
        q += __shfl_xor_sync(0xffffffffu, q, o);
    }
    __shared__ float ws[8], wq[8];
    if ((tid & 31) == 0) { ws[tid >> 5] = s; wq[tid >> 5] = q; }
    __syncthreads();
    if (tid == 0) {
        float S = 0.f, Q = 0.f;
#pragma unroll
        for (int i = 0; i < 8; ++i) { S += ws[i]; Q += wq[i]; }
        int bid = (blockIdx.z * gridDim.y + blockIdx.y) * gridDim.x + blockIdx.x;
        g_psum[bid] = S; g_psq[bid] = Q;
    }
}

// ---------------------------------------------------------------------------
// Kernel 2: split W into bf16 hi/lo + coalesced per-row sums.
// One block per row u; 512 threads read the row coalesced.
// ---------------------------------------------------------------------------
__global__ __launch_bounds__(512) void convert_w(const float* __restrict__ W) {
    const int u = blockIdx.x, t = threadIdx.x;
    float v = W[u * T_DIM + t];
    __nv_bfloat16 h = __float2bfloat16_rn(v);
    g_whi[u * T_DIM + t] = h;
    g_wlo[u * T_DIM + t] = __float2bfloat16_rn(v - __bfloat162float(h));

    float s = v;
#pragma unroll
    for (int o = 16; o > 0; o >>= 1) s += __shfl_xor_sync(0xffffffffu, s, o);
    __shared__ float ws[16];
    if ((t & 31) == 0) ws[t >> 5] = s;
    __syncthreads();
    if (t == 0) {
        float S = 0.f;
#pragma unroll
        for (int i = 0; i < 16; ++i) S += ws[i];
        g_wrowsum[u] = S;
    }
}

// ---------------------------------------------------------------------------
// Kernel 3: finalize stats -> scale, per-row combined bias (cheap now)
// ---------------------------------------------------------------------------
__global__ __launch_bounds__(512) void stats_finalize(const float* __restrict__ bias,
                                                      const float* __restrict__ gamma,
                                                      const float* __restrict__ beta) {
    __shared__ double ds[512], dq[512];
    __shared__ float sh_shift;
    const int tid = threadIdx.x;
    double s = 0.0, q = 0.0;
#pragma unroll 4
    for (int j = 0; j < PBLK / 512; ++j) {
        s += (double)g_psum[tid + j * 512];
        q += (double)g_psq[tid + j * 512];
    }
    ds[tid] = s; dq[tid] = q;
    __syncthreads();
#pragma unroll
    for (int o = 256; o > 0; o >>= 1) {
        if (tid < o) { ds[tid] += ds[tid + o]; dq[tid] += dq[tid + o]; }
        __syncthreads();
    }
    if (tid == 0) {
        double mean = ds[0] / (double)NELEM;
        double var  = dq[0] / (double)NELEM - mean * mean;
        float inv = 1.0f / sqrtf((float)var + EPSV);
        float sc  = gamma[0] * inv;
        g_scale  = sc;
        sh_shift = beta[0] - sc * (float)mean;
    }
    __syncthreads();
    g_cbias[tid] = bias[tid] + sh_shift * g_wrowsum[tid];
}

// ---------------------------------------------------------------------------
// Kernel 4: mma.sync bf16 GEMM. CTA 128(M=u) x 128(N=f), BK=32, 4 stages,
// 512 threads (16 warps, 4m x 4n, warp tile 32x32).
// SMEM row layout per tile row: [hi 64B | lo 64B] = 128B, XOR-swizzled.
// ---------------------------------------------------------------------------
#define GM 128
#define GN 128
#define BK 32
#define NIT (T_DIM / BK)       // 16
#define STG 32768              // 16KB A + 16KB B per stage
#define NSTAGE 4
#define SM_DYN (NSTAGE * STG)  // 131072

static __device__ __forceinline__ uint32_t smem_u32(const void* p) {
    uint32_t a;
    asm("{ .reg .u64 t; cvta.to.shared.u64 t, %1; cvt.u32.u64 %0, t; }" : "=r"(a) : "l"(p));
    return a;
}
static __device__ __forceinline__ void cpa16(uint32_t s, const void* g) {
    asm volatile("cp.async.cg.shared.global [%0], [%1], 16;" :: "r"(s), "l"(g));
}
static __device__ __forceinline__ void cpa_commit() {
    asm volatile("cp.async.commit_group;" ::: "memory");
}
template <int N> static __device__ __forceinline__ void cpa_wait() {
    asm volatile("cp.async.wait_group %0;" :: "n"(N) : "memory");
}
static __device__ __forceinline__ void ldmx4(uint32_t* r, uint32_t a) {
    asm volatile("ldmatrix.sync.aligned.m8n8.x4.shared.b16 {%0,%1,%2,%3}, [%4];"
        : "=r"(r[0]), "=r"(r[1]), "=r"(r[2]), "=r"(r[3]) : "r"(a));
}
static __device__ __forceinline__ void mma16816(float* d, const uint32_t* a,
                                                uint32_t b0, uint32_t b1) {
    asm volatile("mma.sync.aligned.m16n8k16.row.col.f32.bf16.bf16.f32 "
        "{%0,%1,%2,%3}, {%4,%5,%6,%7}, {%8,%9}, {%0,%1,%2,%3};"
        : "+f"(d[0]), "+f"(d[1]), "+f"(d[2]), "+f"(d[3])
        : "r"(a[0]), "r"(a[1]), "r"(a[2]), "r"(a[3]), "r"(b0), "r"(b1));
}

// 2048 x 16B chunks per stage (1024 A + 1024 B); 512 threads -> 2+2 each.
static __device__ __forceinline__ void load_stage(uint32_t sb, int m0, size_t bbase,
                                                  int k0, int tid) {
#pragma unroll
    for (int i = 0; i < 2; ++i) {
        int idx = tid + i * 512;
        int row = idx >> 3, c = idx & 7;
        uint32_t sw = (uint32_t)(row * 128) + (((uint32_t)(c * 16)) ^ ((row & 7) << 4));
        const __nv_bfloat16* src = (c < 4)
            ? (g_whi + (size_t)(m0 + row) * T_DIM + k0 + c * 8)
            : (g_wlo + (size_t)(m0 + row) * T_DIM + k0 + (c - 4) * 8);
        cpa16(sb + sw, src);
    }
#pragma unroll
    for (int i = 0; i < 2; ++i) {
        int idx = tid + i * 512;
        int row = idx >> 3, c = idx & 7;
        uint32_t sw = (uint32_t)(row * 128) + (((uint32_t)(c * 16)) ^ ((row & 7) << 4));
        const __nv_bfloat16* src = (c < 4)
            ? (g_xhiT + bbase + (size_t)row * T_DIM + k0 + c * 8)
            : (g_xloT + bbase + (size_t)row * T_DIM + k0 + (c - 4) * 8);
        cpa16(sb + 16384 + sw, src);
    }
}

__global__ __launch_bounds__(512, 1) void gemm_tc(const float* __restrict__ x,
                                                  float* __restrict__ out) {
    extern __shared__ __align__(16) char smem[];
    const uint32_t sbase = smem_u32(smem);
    const int tid = threadIdx.x;
    const int n0 = blockIdx.x * GN;
    const int m0 = blockIdx.y * GM;
    const int b  = blockIdx.z;
    const size_t bbase = ((size_t)b * F_DIM + n0) * T_DIM;

    const int lane = tid & 31, w = tid >> 5;
    const int wm = w & 3;        // 0..3 -> 32-row m slice
    const int wn = w >> 2;       // 0..3 -> 32-col n slice
    const uint32_t X = (uint32_t)(((lane >> 4) ^ (lane & 7)) << 4);
    const uint32_t PA0 = (uint32_t)((wm * 32 + (lane & 15)) * 128);
    const uint32_t PA1 = PA0 + 16 * 128;
    uint32_t PB[2];
#pragma unroll
    for (int g = 0; g < 2; ++g)
        PB[g] = 16384u + (uint32_t)((wn * 32 + g * 16 + (lane & 15)) * 128);

    float acc[2][4][4];
#pragma unroll
    for (int mi = 0; mi < 2; ++mi)
#pragma unroll
        for (int nj = 0; nj < 4; ++nj)
#pragma unroll
            for (int e = 0; e < 4; ++e) acc[mi][nj][e] = 0.f;

    // prologue: stages 0, 1, 2
    load_stage(sbase,           m0, bbase, 0,      tid); cpa_commit();
    load_stage(sbase + STG,     m0, bbase, BK,     tid); cpa_commit();
    load_stage(sbase + 2 * STG, m0, bbase, 2 * BK, tid); cpa_commit();

    int stage = 0;
#pragma unroll 1
    for (int it = 0; it < NIT; ++it) {
        if (it + 2 < NIT)      cpa_wait<2>();
        else if (it + 1 < NIT) cpa_wait<1>();
        else                   cpa_wait<0>();
        __syncthreads();
        if (it + 3 < NIT) {
            int ns = stage + 3; if (ns >= NSTAGE) ns -= NSTAGE;
            load_stage(sbase + ns * STG, m0, bbase, (it + 3) * BK, tid);
            cpa_commit();
        }
        const uint32_t sb = sbase + stage * STG;
        const uint32_t sA0 = sb + PA0, sA1 = sb + PA1;

#pragma unroll
        for (int kk = 0; kk < 2; ++kk) {
            const uint32_t ch = (uint32_t)(kk * 32);       // hi bytes
            const uint32_t cl = ch + 64u;                  // lo bytes
            uint32_t ah[2][4], al[2][4], bh[2][4], bl[2][4];
            ldmx4(ah[0], sA0 + (ch ^ X));
            ldmx4(al[0], sA0 + (cl ^ X));
            ldmx4(ah[1], sA1 + (ch ^ X));
            ldmx4(al[1], sA1 + (cl ^ X));
#pragma unroll
            for (int g = 0; g < 2; ++g) {
                ldmx4(bh[g], sb + PB[g] + (ch ^ X));
                ldmx4(bl[g], sb + PB[g] + (cl ^ X));
            }
#pragma unroll
            for (int g = 0; g < 2; ++g) {
#pragma unroll
                for (int mi = 0; mi < 2; ++mi) {
                    mma16816(acc[mi][2 * g],     ah[mi], bh[g][0], bh[g][2]);
                    mma16816(acc[mi][2 * g],     al[mi], bh[g][0], bh[g][2]);
                    mma16816(acc[mi][2 * g],     ah[mi], bl[g][0], bl[g][2]);
                    mma16816(acc[mi][2 * g + 1], ah[mi], bh[g][1], bh[g][3]);
                    mma16816(acc[mi][2 * g + 1], al[mi], bh[g][1], bh[g][3]);
                    mma16816(acc[mi][2 * g + 1], ah[mi], bl[g][1], bl[g][3]);
                }
            }
        }
        ++stage; if (stage == NSTAGE) stage = 0;
    }

    // ---- epilogue: out = x + relu(sc*acc + cbias[row]) ----
    const float sc = g_scale;
    const int rbase = m0 + wm * 32 + (lane >> 2);
    const int cbase = n0 + wn * 32 + (lane & 3) * 2;
#pragma unroll
    for (int mi = 0; mi < 2; ++mi) {
        const int r0 = rbase + mi * 16;
        const float cb0 = g_cbias[r0];
        const float cb1 = g_cbias[r0 + 8];
        const float* x0 = x + ((size_t)b * T_DIM + r0) * F_DIM;
        float* o0 = out + ((size_t)b * T_DIM + r0) * F_DIM;
#pragma unroll
        for (int nj = 0; nj < 4; ++nj) {
            const int c = cbase + nj * 8;
            float2 xv0 = *(const float2*)(x0 + c);
            float2 xv1 = *(const float2*)(x0 + 8 * F_DIM + c);
            float2 r0v, r1v;
            r0v.x = xv0.x + fmaxf(fmaf(sc, acc[mi][nj][0], cb0), 0.f);
            r0v.y = xv0.y + fmaxf(fmaf(sc, acc[mi][nj][1], cb0), 0.f);
            r1v.x = xv1.x + fmaxf(fmaf(sc, acc[mi][nj][2], cb1), 0.f);
            r1v.y = xv1.y + fmaxf(fmaf(sc, acc[mi][nj][3], cb1), 0.f);
            *(float2*)(o0 + c) = r0v;
            *(float2*)(o0 + 8 * F_DIM + c) = r1v;
        }
    }
}

// ---------------------------------------------------------------------------
extern "C" void kernel_launch(void* const* d_in, const int* in_sizes, int n_in,
                              void* d_out, int out_size) {
    const float* x     = (const float*)d_in[0];
    const float* W     = (const float*)d_in[1];
    const float* bias  = (const float*)d_in[2];
    const float* gamma = (const float*)d_in[3];
    const float* beta  = (const float*)d_in[4];
    float* out = (float*)d_out;

    cudaFuncSetAttribute(gemm_tc, cudaFuncAttributeMaxDynamicSharedMemorySize, SM_DYN);

    dim3 cgrid(F_DIM / 32, T_DIM / 32, B_DIM);      // (32, 16, 64)
    convert_x<<<cgrid, dim3(32, 8)>>>(x);
    convert_w<<<T_DIM, 512>>>(W);
    stats_finalize<<<1, 512>>>(bias, gamma, beta);

    dim3 ggrid(F_DIM / GN, T_DIM / GM, B_DIM);      // (8, 4, 64)
    gemm_tc<<<ggrid, 512, SM_DYN>>>(x, out);
}

// round 14
// speedup vs baseline: 2.2840x; 1.3559x over previous
#include <cuda_runtime.h>
#include <cuda_fp16.h>
#include <cstdint>

// out[b,u,f] = x[b,u,f] + relu(scale * sum_t W[u,t]*x[b,t,f] + cbias[u])
//   scale = gamma*rsqrt(var+eps), cbias[u] = b[u] + (beta - scale*mean)*rowsumW[u]
// GEMM on tensor cores (mma.sync fp16) with W split hi/lo fp16, x single fp16:
//   W@x ~= Whi@x_f16 + Wlo@x_f16   (dropped: W@(x - x_f16), rel ~1e-4)

#define B_DIM 64
#define T_DIM 512
#define F_DIM 1024
#define NELEM (B_DIM * T_DIM * F_DIM)
#define EPSV 1e-5f
#define PBLK 32768

// ----- device scratch (no allocation allowed) -----
__device__ __half g_xT[(size_t)B_DIM * F_DIM * T_DIM];   // [b, f, t] fp16
__device__ __half g_whi[T_DIM * T_DIM];                  // [u, t]
__device__ __half g_wlo[T_DIM * T_DIM];
__device__ float g_wrowsum[T_DIM];
__device__ float g_psum[PBLK];
__device__ float g_psq[PBLK];
__device__ float g_scale;
__device__ float g_cbias[T_DIM];

// ---------------------------------------------------------------------------
// Kernel 1: convert x to fp16 TRANSPOSED to [b, f, t]; fused stats partials.
// ---------------------------------------------------------------------------
__global__ __launch_bounds__(256) void convert_x(const float* __restrict__ x) {
    __shared__ __half hs[32][33];
    const int tx = threadIdx.x, ty = threadIdx.y;   // (32, 8)
    const int f0 = blockIdx.x * 32, t0 = blockIdx.y * 32, b = blockIdx.z;
    const float* xb = x + (size_t)b * T_DIM * F_DIM;

    float s = 0.f, q = 0.f;
#pragma unroll
    for (int j = 0; j < 4; ++j) {
        float v = xb[(size_t)(t0 + ty + 8 * j) * F_DIM + f0 + tx];
        s += v; q += v * v;
        hs[ty + 8 * j][tx] = __float2half_rn(v);
    }
    __syncthreads();
    const size_t ob = ((size_t)b * F_DIM + f0) * T_DIM + t0;
#pragma unroll
    for (int j = 0; j < 4; ++j)
        g_xT[ob + (size_t)(ty + 8 * j) * T_DIM + tx] = hs[tx][ty + 8 * j];

    const int tid = ty * 32 + tx;
#pragma unroll
    for (int o = 16; o > 0; o >>= 1) {
        s += __shfl_xor_sync(0xffffffffu, s, o);
        q += __shfl_xor_sync(0xffffffffu, q, o);
    }
    __shared__ float ws[8], wq[8];
    if ((tid & 31) == 0) { ws[tid >> 5] = s; wq[tid >> 5] = q; }
    __syncthreads();
    if (tid == 0) {
        float S = 0.f, Q = 0.f;
#pragma unroll
        for (int i = 0; i < 8; ++i) { S += ws[i]; Q += wq[i]; }
        int bid = (blockIdx.z * gridDim.y + blockIdx.y) * gridDim.x + blockIdx.x;
        g_psum[bid] = S; g_psq[bid] = Q;
    }
}

// ---------------------------------------------------------------------------
// Kernel 2: split W into fp16 hi/lo + coalesced per-row sums.
// ---------------------------------------------------------------------------
__global__ __launch_bounds__(512) void convert_w(const float* __restrict__ W) {
    const int u = blockIdx.x, t = threadIdx.x;
    float v = W[u * T_DIM + t];
    __half h = __float2half_rn(v);
    g_whi[u * T_DIM + t] = h;
    g_wlo[u * T_DIM + t] = __float2half_rn(v - __half2float(h));

    float s = v;
#pragma unroll
    for (int o = 16; o > 0; o >>= 1) s += __shfl_xor_sync(0xffffffffu, s, o);
    __shared__ float ws[16];
    if ((t & 31) == 0) ws[t >> 5] = s;
    __syncthreads();
    if (t == 0) {
        float S = 0.f;
#pragma unroll
        for (int i = 0; i < 16; ++i) S += ws[i];
        g_wrowsum[u] = S;
    }
}

// ---------------------------------------------------------------------------
// Kernel 3: finalize stats -> scale, per-row combined bias
// ---------------------------------------------------------------------------
__global__ __launch_bounds__(512) void stats_finalize(const float* __restrict__ bias,
                                                      const float* __restrict__ gamma,
                                                      const float* __restrict__ beta) {
    __shared__ double ds[512], dq[512];
    __shared__ float sh_shift;
    const int tid = threadIdx.x;
    double s = 0.0, q = 0.0;
#pragma unroll 4
    for (int j = 0; j < PBLK / 512; ++j) {
        s += (double)g_psum[tid + j * 512];
        q += (double)g_psq[tid + j * 512];
    }
    ds[tid] = s; dq[tid] = q;
    __syncthreads();
#pragma unroll
    for (int o = 256; o > 0; o >>= 1) {
        if (tid < o) { ds[tid] += ds[tid + o]; dq[tid] += dq[tid + o]; }
        __syncthreads();
    }
    if (tid == 0) {
        double mean = ds[0] / (double)NELEM;
        double var  = dq[0] / (double)NELEM - mean * mean;
        float inv = 1.0f / sqrtf((float)var + EPSV);
        float sc  = gamma[0] * inv;
        g_scale  = sc;
        sh_shift = beta[0] - sc * (float)mean;
    }
    __syncthreads();
    g_cbias[tid] = bias[tid] + sh_shift * g_wrowsum[tid];
}

// ---------------------------------------------------------------------------
// Kernel 4: mma.sync fp16 GEMM. CTA 128(M=u) x 128(N=f), BK=64, 4 stages,
// 512 threads (16 warps, 4m x 4n, warp tile 32x32).
// Stage layout: A = 256 rows x 128B (rows 0..127 Whi, 128..255 Wlo),
//               B = 128 rows x 128B (x fp16, k-major). XOR swizzle per 128B row.
// ---------------------------------------------------------------------------
#define GM 128
#define GN 128
#define BK 64
#define NIT (T_DIM / BK)       // 8
#define ASZ 32768
#define BSZ 16384
#define STG (ASZ + BSZ)        // 49152
#define NSTAGE 4
#define SM_DYN (NSTAGE * STG)  // 196608

static __device__ __forceinline__ uint32_t smem_u32(const void* p) {
    uint32_t a;
    asm("{ .reg .u64 t; cvta.to.shared.u64 t, %1; cvt.u32.u64 %0, t; }" : "=r"(a) : "l"(p));
    return a;
}
static __device__ __forceinline__ void cpa16(uint32_t s, const void* g) {
    asm volatile("cp.async.cg.shared.global [%0], [%1], 16;" :: "r"(s), "l"(g));
}
static __device__ __forceinline__ void cpa_commit() {
    asm volatile("cp.async.commit_group;" ::: "memory");
}
template <int N> static __device__ __forceinline__ void cpa_wait() {
    asm volatile("cp.async.wait_group %0;" :: "n"(N) : "memory");
}
static __device__ __forceinline__ void ldmx4(uint32_t* r, uint32_t a) {
    asm volatile("ldmatrix.sync.aligned.m8n8.x4.shared.b16 {%0,%1,%2,%3}, [%4];"
        : "=r"(r[0]), "=r"(r[1]), "=r"(r[2]), "=r"(r[3]) : "r"(a));
}
static __device__ __forceinline__ void mma16816(float* d, const uint32_t* a,
                                                uint32_t b0, uint32_t b1) {
    asm volatile("mma.sync.aligned.m16n8k16.row.col.f32.f16.f16.f32 "
        "{%0,%1,%2,%3}, {%4,%5,%6,%7}, {%8,%9}, {%0,%1,%2,%3};"
        : "+f"(d[0]), "+f"(d[1]), "+f"(d[2]), "+f"(d[3])
        : "r"(a[0]), "r"(a[1]), "r"(a[2]), "r"(a[3]), "r"(b0), "r"(b1));
}

// Per stage: A 2048 16B-chunks + B 1024 chunks; 512 threads -> 4 + 2 each.
static __device__ __forceinline__ void load_stage(uint32_t sb, int m0, size_t bbase,
                                                  int k0, int tid) {
#pragma unroll
    for (int i = 0; i < 2; ++i) {            // Whi -> smem rows 0..127
        int idx = tid + i * 512;
        int row = idx >> 3, c = idx & 7;
        uint32_t sw = (uint32_t)(row * 128) + (((uint32_t)(c * 16)) ^ ((row & 7) << 4));
        cpa16(sb + sw, g_whi + (size_t)(m0 + row) * T_DIM + k0 + c * 8);
    }
#pragma unroll
    for (int i = 0; i < 2; ++i) {            // Wlo -> smem rows 128..255
        int idx = tid + i * 512;
        int row = idx >> 3, c = idx & 7;
        uint32_t sw = (uint32_t)((row + 128) * 128) + (((uint32_t)(c * 16)) ^ ((row & 7) << 4));
        cpa16(sb + sw, g_wlo + (size_t)(m0 + row) * T_DIM + k0 + c * 8);
    }
#pragma unroll
    for (int i = 0; i < 2; ++i) {            // x -> B rows 0..127
        int idx = tid + i * 512;
        int row = idx >> 3, c = idx & 7;
        uint32_t sw = (uint32_t)(row * 128) + (((uint32_t)(c * 16)) ^ ((row & 7) << 4));
        cpa16(sb + ASZ + sw, g_xT + bbase + (size_t)row * T_DIM + k0 + c * 8);
    }
}

__global__ __launch_bounds__(512, 1) void gemm_tc(const float* __restrict__ x,
                                                  float* __restrict__ out) {
    extern __shared__ __align__(16) char smem[];
    const uint32_t sbase = smem_u32(smem);
    const int tid = threadIdx.x;
    const int n0 = blockIdx.x * GN;
    const int m0 = blockIdx.y * GM;
    const int b  = blockIdx.z;
    const size_t bbase = ((size_t)b * F_DIM + n0) * T_DIM;

    const int lane = tid & 31, w = tid >> 5;
    const int wm = w & 3;        // 0..3 -> 32-row m slice
    const int wn = w >> 2;       // 0..3 -> 32-col n slice
    const uint32_t X = (uint32_t)(((lane >> 4) ^ (lane & 7)) << 4);
    const uint32_t PA0 = (uint32_t)((wm * 32 + (lane & 15)) * 128);
    const uint32_t PA1 = PA0 + 16 * 128;
    uint32_t PB[2];
#pragma unroll
    for (int g = 0; g < 2; ++g)
        PB[g] = (uint32_t)ASZ + (uint32_t)((wn * 32 + g * 16 + (lane & 15)) * 128);

    float acc[2][4][4];
#pragma unroll
    for (int mi = 0; mi < 2; ++mi)
#pragma unroll
        for (int nj = 0; nj < 4; ++nj)
#pragma unroll
            for (int e = 0; e < 4; ++e) acc[mi][nj][e] = 0.f;

    // prologue: stages 0, 1, 2
    load_stage(sbase,           m0, bbase, 0,      tid); cpa_commit();
    load_stage(sbase + STG,     m0, bbase, BK,     tid); cpa_commit();
    load_stage(sbase + 2 * STG, m0, bbase, 2 * BK, tid); cpa_commit();

    int stage = 0;
#pragma unroll 1
    for (int it = 0; it < NIT; ++it) {
        if (it + 2 < NIT)      cpa_wait<2>();
        else if (it + 1 < NIT) cpa_wait<1>();
        else                   cpa_wait<0>();
        __syncthreads();
        if (it + 3 < NIT) {
            int ns = stage + 3; if (ns >= NSTAGE) ns -= NSTAGE;
            load_stage(sbase + ns * STG, m0, bbase, (it + 3) * BK, tid);
            cpa_commit();
        }
        const uint32_t sb = sbase + stage * STG;
        const uint32_t sA0 = sb + PA0, sA1 = sb + PA1;

#pragma unroll
        for (int kk = 0; kk < 4; ++kk) {
            const uint32_t ch = (uint32_t)(kk * 32);       // k16 chunk within 128B row
            uint32_t ah[2][4], al[2][4], bx[2][4];
            ldmx4(ah[0], sA0 + (ch ^ X));
            ldmx4(ah[1], sA1 + (ch ^ X));
            ldmx4(al[0], sA0 + 16384u + (ch ^ X));         // Wlo rows (+128 rows)
            ldmx4(al[1], sA1 + 16384u + (ch ^ X));
#pragma unroll
            for (int g = 0; g < 2; ++g)
                ldmx4(bx[g], sb + PB[g] + (ch ^ X));
#pragma unroll
            for (int g = 0; g < 2; ++g) {
#pragma unroll
                for (int mi = 0; mi < 2; ++mi) {
                    mma16816(acc[mi][2 * g],     ah[mi], bx[g][0], bx[g][2]);
                    mma16816(acc[mi][2 * g],     al[mi], bx[g][0], bx[g][2]);
                    mma16816(acc[mi][2 * g + 1], ah[mi], bx[g][1], bx[g][3]);
                    mma16816(acc[mi][2 * g + 1], al[mi], bx[g][1], bx[g][3]);
                }
            }
        }
        ++stage; if (stage == NSTAGE) stage = 0;
    }

    // ---- epilogue: out = x + relu(sc*acc + cbias[row]) ----
    const float sc = g_scale;
    const int rbase = m0 + wm * 32 + (lane >> 2);
    const int cbase = n0 + wn * 32 + (lane & 3) * 2;
#pragma unroll
    for (int mi = 0; mi < 2; ++mi) {
        const int r0 = rbase + mi * 16;
        const float cb0 = g_cbias[r0];
        const float cb1 = g_cbias[r0 + 8];
        const float* x0 = x + ((size_t)b * T_DIM + r0) * F_DIM;
        float* o0 = out + ((size_t)b * T_DIM + r0) * F_DIM;
#pragma unroll
        for (int nj = 0; nj < 4; ++nj) {
            const int c = cbase + nj * 8;
            float2 xv0 = *(const float2*)(x0 + c);
            float2 xv1 = *(const float2*)(x0 + 8 * F_DIM + c);
            float2 r0v, r1v;
            r0v.x = xv0.x + fmaxf(fmaf(sc, acc[mi][nj][0], cb0), 0.f);
            r0v.y = xv0.y + fmaxf(fmaf(sc, acc[mi][nj][1], cb0), 0.f);
            r1v.x = xv1.x + fmaxf(fmaf(sc, acc[mi][nj][2], cb1), 0.f);
            r1v.y = xv1.y + fmaxf(fmaf(sc, acc[mi][nj][3], cb1), 0.f);
            *(float2*)(o0 + c) = r0v;
            *(float2*)(o0 + 8 * F_DIM + c) = r1v;
        }
    }
}

// ---------------------------------------------------------------------------
extern "C" void kernel_launch(void* const* d_in, const int* in_sizes, int n_in,
                              void* d_out, int out_size) {
    const float* x     = (const float*)d_in[0];
    const float* W     = (const float*)d_in[1];
    const float* bias  = (const float*)d_in[2];
    const float* gamma = (const float*)d_in[3];
    const float* beta  = (const float*)d_in[4];
    float* out = (float*)d_out;

    cudaFuncSetAttribute(gemm_tc, cudaFuncAttributeMaxDynamicSharedMemorySize, SM_DYN);

    dim3 cgrid(F_DIM / 32, T_DIM / 32, B_DIM);      // (32, 16, 64)
    convert_x<<<cgrid, dim3(32, 8)>>>(x);
    convert_w<<<T_DIM, 512>>>(W);
    stats_finalize<<<1, 512>>>(bias, gamma, beta);

    dim3 ggrid(F_DIM / GN, T_DIM / GM, B_DIM);      // (8, 4, 64)
    gemm_tc<<<ggrid, 512, SM_DYN>>>(x, out);
}

// round 15
// speedup vs baseline: 2.2951x; 1.0049x over previous
#include <cuda_runtime.h>
#include <cuda_fp16.h>
#include <cstdint>

// out[b,u,f] = x[b,u,f] + relu(scale * sum_t W[u,t]*x[b,t,f] + cbias[u])
//   scale = gamma*rsqrt(var+eps), cbias[u] = b[u] + (beta - scale*mean)*rowsumW[u]
// GEMM on tensor cores (mma.sync fp16) with W split hi/lo fp16, x single fp16:
//   W@x ~= Whi@x_f16 + Wlo@x_f16   (dropped: W@(x - x_f16), rel ~1e-4)

#define B_DIM 64
#define T_DIM 512
#define F_DIM 1024
#define NELEM (B_DIM * T_DIM * F_DIM)
#define EPSV 1e-5f
#define PBLK 32768

// ----- device scratch (no allocation allowed) -----
__device__ __half g_xT[(size_t)B_DIM * F_DIM * T_DIM];   // [b, f, t] fp16
__device__ __half g_whi[T_DIM * T_DIM];                  // [u, t]
__device__ __half g_wlo[T_DIM * T_DIM];
__device__ float g_wrowsum[T_DIM];
__device__ float g_psum[PBLK];
__device__ float g_psq[PBLK];
__device__ float g_scale;
__device__ float g_cbias[T_DIM];

// ---------------------------------------------------------------------------
// Kernel 1: convert x to fp16 TRANSPOSED to [b, f, t]; fused stats partials.
// ---------------------------------------------------------------------------
__global__ __launch_bounds__(256) void convert_x(const float* __restrict__ x) {
    __shared__ __half hs[32][33];
    const int tx = threadIdx.x, ty = threadIdx.y;   // (32, 8)
    const int f0 = blockIdx.x * 32, t0 = blockIdx.y * 32, b = blockIdx.z;
    const float* xb = x + (size_t)b * T_DIM * F_DIM;

    float s = 0.f, q = 0.f;
#pragma unroll
    for (int j = 0; j < 4; ++j) {
        float v = xb[(size_t)(t0 + ty + 8 * j) * F_DIM + f0 + tx];
        s += v; q += v * v;
        hs[ty + 8 * j][tx] = __float2half_rn(v);
    }
    __syncthreads();
    const size_t ob = ((size_t)b * F_DIM + f0) * T_DIM + t0;
#pragma unroll
    for (int j = 0; j < 4; ++j)
        g_xT[ob + (size_t)(ty + 8 * j) * T_DIM + tx] = hs[tx][ty + 8 * j];

    const int tid = ty * 32 + tx;
#pragma unroll
    for (int o = 16; o > 0; o >>= 1) {
        s += __shfl_xor_sync(0xffffffffu, s, o);
        q += __shfl_xor_sync(0xffffffffu, q, o);
    }
    __shared__ float ws[8], wq[8];
    if ((tid & 31) == 0) { ws[tid >> 5] = s; wq[tid >> 5] = q; }
    __syncthreads();
    if (tid == 0) {
        float S = 0.f, Q = 0.f;
#pragma unroll
        for (int i = 0; i < 8; ++i) { S += ws[i]; Q += wq[i]; }
        int bid = (blockIdx.z * gridDim.y + blockIdx.y) * gridDim.x + blockIdx.x;
        g_psum[bid] = S; g_psq[bid] = Q;
    }
}

// ---------------------------------------------------------------------------
// Kernel 2: split W into fp16 hi/lo + coalesced per-row sums.
// ---------------------------------------------------------------------------
__global__ __launch_bounds__(512) void convert_w(const float* __restrict__ W) {
    const int u = blockIdx.x, t = threadIdx.x;
    float v = W[u * T_DIM + t];
    __half h = __float2half_rn(v);
    g_whi[u * T_DIM + t] = h;
    g_wlo[u * T_DIM + t] = __float2half_rn(v - __half2float(h));

    float s = v;
#pragma unroll
    for (int o = 16; o > 0; o >>= 1) s += __shfl_xor_sync(0xffffffffu, s, o);
    __shared__ float ws[16];
    if ((t & 31) == 0) ws[t >> 5] = s;
    __syncthreads();
    if (t == 0) {
        float S = 0.f;
#pragma unroll
        for (int i = 0; i < 16; ++i) S += ws[i];
        g_wrowsum[u] = S;
    }
}

// ---------------------------------------------------------------------------
// Kernel 3: finalize stats -> scale, per-row combined bias
// ---------------------------------------------------------------------------
__global__ __launch_bounds__(512) void stats_finalize(const float* __restrict__ bias,
                                                      const float* __restrict__ gamma,
                                                      const float* __restrict__ beta) {
    __shared__ double ds[512], dq[512];
    __shared__ float sh_shift;
    const int tid = threadIdx.x;
    double s = 0.0, q = 0.0;
#pragma unroll 4
    for (int j = 0; j < PBLK / 512; ++j) {
        s += (double)g_psum[tid + j * 512];
        q += (double)g_psq[tid + j * 512];
    }
    ds[tid] = s; dq[tid] = q;
    __syncthreads();
#pragma unroll
    for (int o = 256; o > 0; o >>= 1) {
        if (tid < o) { ds[tid] += ds[tid + o]; dq[tid] += dq[tid + o]; }
        __syncthreads();
    }
    if (tid == 0) {
        double mean = ds[0] / (double)NELEM;
        double var  = dq[0] / (double)NELEM - mean * mean;
        float inv = 1.0f / sqrtf((float)var + EPSV);
        float sc  = gamma[0] * inv;
        g_scale  = sc;
        sh_shift = beta[0] - sc * (float)mean;
    }
    __syncthreads();
    g_cbias[tid] = bias[tid] + sh_shift * g_wrowsum[tid];
}

// ---------------------------------------------------------------------------
// Kernel 4: mma.sync fp16 GEMM. CTA 128(M=u) x 128(N=f), BK=64, 4 stages,
// 512 threads (16 warps, 4m x 4n, warp tile 32x32).
// Stage layout: A = 256 rows x 128B (rows 0..127 Whi, 128..255 Wlo),
//               B = 128 rows x 128B (x fp16, k-major). XOR swizzle per 128B row.
// ---------------------------------------------------------------------------
#define GM 128
#define GN 128
#define BK 64
#define NIT (T_DIM / BK)       // 8
#define ASZ 32768
#define BSZ 16384
#define STG (ASZ + BSZ)        // 49152
#define NSTAGE 4
#define SM_DYN (NSTAGE * STG)  // 196608

static __device__ __forceinline__ uint32_t smem_u32(const void* p) {
    uint32_t a;
    asm("{ .reg .u64 t; cvta.to.shared.u64 t, %1; cvt.u32.u64 %0, t; }" : "=r"(a) : "l"(p));
    return a;
}
static __device__ __forceinline__ void cpa16(uint32_t s, const void* g) {
    asm volatile("cp.async.cg.shared.global [%0], [%1], 16;" :: "r"(s), "l"(g));
}
static __device__ __forceinline__ void cpa_commit() {
    asm volatile("cp.async.commit_group;" ::: "memory");
}
template <int N> static __device__ __forceinline__ void cpa_wait() {
    asm volatile("cp.async.wait_group %0;" :: "n"(N) : "memory");
}
static __device__ __forceinline__ void ldmx4(uint32_t* r, uint32_t a) {
    asm volatile("ldmatrix.sync.aligned.m8n8.x4.shared.b16 {%0,%1,%2,%3}, [%4];"
        : "=r"(r[0]), "=r"(r[1]), "=r"(r[2]), "=r"(r[3]) : "r"(a));
}
static __device__ __forceinline__ void mma16816(float* d, const uint32_t* a,
                                                uint32_t b0, uint32_t b1) {
    asm volatile("mma.sync.aligned.m16n8k16.row.col.f32.f16.f16.f32 "
        "{%0,%1,%2,%3}, {%4,%5,%6,%7}, {%8,%9}, {%0,%1,%2,%3};"
        : "+f"(d[0]), "+f"(d[1]), "+f"(d[2]), "+f"(d[3])
        : "r"(a[0]), "r"(a[1]), "r"(a[2]), "r"(a[3]), "r"(b0), "r"(b1));
}

// Per stage: A 2048 16B-chunks + B 1024 chunks; 512 threads -> 4 + 2 each.
static __device__ __forceinline__ void load_stage(uint32_t sb, int m0, size_t bbase,
                                                  int k0, int tid) {
#pragma unroll
    for (int i = 0; i < 2; ++i) {            // Whi -> smem rows 0..127
        int idx = tid + i * 512;
        int row = idx >> 3, c = idx & 7;
        uint32_t sw = (uint32_t)(row * 128) + (((uint32_t)(c * 16)) ^ ((row & 7) << 4));
        cpa16(sb + sw, g_whi + (size_t)(m0 + row) * T_DIM + k0 + c * 8);
    }
#pragma unroll
    for (int i = 0; i < 2; ++i) {            // Wlo -> smem rows 128..255
        int idx = tid + i * 512;
        int row = idx >> 3, c = idx & 7;
        uint32_t sw = (uint32_t)((row + 128) * 128) + (((uint32_t)(c * 16)) ^ ((row & 7) << 4));
        cpa16(sb + sw, g_wlo + (size_t)(m0 + row) * T_DIM + k0 + c * 8);
    }
#pragma unroll
    for (int i = 0; i < 2; ++i) {            // x -> B rows 0..127
        int idx = tid + i * 512;
        int row = idx >> 3, c = idx & 7;
        uint32_t sw = (uint32_t)(row * 128) + (((uint32_t)(c * 16)) ^ ((row & 7) << 4));
        cpa16(sb + ASZ + sw, g_xT + bbase + (size_t)row * T_DIM + k0 + c * 8);
    }
}

__global__ __launch_bounds__(512, 1) void gemm_tc(const float* __restrict__ x,
                                                  float* __restrict__ out) {
    extern __shared__ __align__(16) char smem[];
    const uint32_t sbase = smem_u32(smem);
    const int tid = threadIdx.x;
    const int n0 = blockIdx.x * GN;
    const int m0 = blockIdx.y * GM;
    const int b  = blockIdx.z;
    const size_t bbase = ((size_t)b * F_DIM + n0) * T_DIM;

    const int lane = tid & 31, w = tid >> 5;
    const int wm = w & 3;        // 0..3 -> 32-row m slice
    const int wn = w >> 2;       // 0..3 -> 32-col n slice
    const uint32_t X = (uint32_t)(((lane >> 4) ^ (lane & 7)) << 4);
    const uint32_t PA0 = (uint32_t)((wm * 32 + (lane & 15)) * 128);
    const uint32_t PA1 = PA0 + 16 * 128;
    uint32_t PB[2];
#pragma unroll
    for (int g = 0; g < 2; ++g)
        PB[g] = (uint32_t)ASZ + (uint32_t)((wn * 32 + g * 16 + (lane & 15)) * 128);

    float acc[2][4][4];
#pragma unroll
    for (int mi = 0; mi < 2; ++mi)
#pragma unroll
        for (int nj = 0; nj < 4; ++nj)
#pragma unroll
            for (int e = 0; e < 4; ++e) acc[mi][nj][e] = 0.f;

    // prologue: stages 0, 1, 2
    load_stage(sbase,           m0, bbase, 0,      tid); cpa_commit();
    load_stage(sbase + STG,     m0, bbase, BK,     tid); cpa_commit();
    load_stage(sbase + 2 * STG, m0, bbase, 2 * BK, tid); cpa_commit();

    int stage = 0;
#pragma unroll 1
    for (int it = 0; it < NIT; ++it) {
        if (it + 2 < NIT)      cpa_wait<2>();
        else if (it + 1 < NIT) cpa_wait<1>();
        else                   cpa_wait<0>();
        __syncthreads();
        if (it + 3 < NIT) {
            int ns = stage + 3; if (ns >= NSTAGE) ns -= NSTAGE;
            load_stage(sbase + ns * STG, m0, bbase, (it + 3) * BK, tid);
            cpa_commit();
        }
        const uint32_t sb = sbase + stage * STG;
        const uint32_t sA0 = sb + PA0, sA1 = sb + PA1;

#pragma unroll
        for (int kk = 0; kk < 4; ++kk) {
            const uint32_t ch = (uint32_t)(kk * 32);       // k16 chunk within 128B row
            uint32_t ah[2][4], al[2][4], bx[2][4];
            ldmx4(ah[0], sA0 + (ch ^ X));
            ldmx4(ah[1], sA1 + (ch ^ X));
            ldmx4(al[0], sA0 + 16384u + (ch ^ X));         // Wlo rows (+128 rows)
            ldmx4(al[1], sA1 + 16384u + (ch ^ X));
#pragma unroll
            for (int g = 0; g < 2; ++g)
                ldmx4(bx[g], sb + PB[g] + (ch ^ X));
#pragma unroll
            for (int g = 0; g < 2; ++g) {
#pragma unroll
                for (int mi = 0; mi < 2; ++mi) {
                    mma16816(acc[mi][2 * g],     ah[mi], bx[g][0], bx[g][2]);
                    mma16816(acc[mi][2 * g],     al[mi], bx[g][0], bx[g][2]);
                    mma16816(acc[mi][2 * g + 1], ah[mi], bx[g][1], bx[g][3]);
                    mma16816(acc[mi][2 * g + 1], al[mi], bx[g][1], bx[g][3]);
                }
            }
        }
        ++stage; if (stage == NSTAGE) stage = 0;
    }

    // ---- epilogue: out = x + relu(sc*acc + cbias[row]) ----
    const float sc = g_scale;
    const int rbase = m0 + wm * 32 + (lane >> 2);
    const int cbase = n0 + wn * 32 + (lane & 3) * 2;
#pragma unroll
    for (int mi = 0; mi < 2; ++mi) {
        const int r0 = rbase + mi * 16;
        const float cb0 = g_cbias[r0];
        const float cb1 = g_cbias[r0 + 8];
        const float* x0 = x + ((size_t)b * T_DIM + r0) * F_DIM;
        float* o0 = out + ((size_t)b * T_DIM + r0) * F_DIM;
#pragma unroll
        for (int nj = 0; nj < 4; ++nj) {
            const int c = cbase + nj * 8;
            float2 xv0 = *(const float2*)(x0 + c);
            float2 xv1 = *(const float2*)(x0 + 8 * F_DIM + c);
            float2 r0v, r1v;
            r0v.x = xv0.x + fmaxf(fmaf(sc, acc[mi][nj][0], cb0), 0.f);
            r0v.y = xv0.y + fmaxf(fmaf(sc, acc[mi][nj][1], cb0), 0.f);
            r1v.x = xv1.x + fmaxf(fmaf(sc, acc[mi][nj][2], cb1), 0.f);
            r1v.y = xv1.y + fmaxf(fmaf(sc, acc[mi][nj][3], cb1), 0.f);
            *(float2*)(o0 + c) = r0v;
            *(float2*)(o0 + 8 * F_DIM + c) = r1v;
        }
    }
}

// ---------------------------------------------------------------------------
extern "C" void kernel_launch(void* const* d_in, const int* in_sizes, int n_in,
                              void* d_out, int out_size) {
    const float* x     = (const float*)d_in[0];
    const float* W     = (const float*)d_in[1];
    const float* bias  = (const float*)d_in[2];
    const float* gamma = (const float*)d_in[3];
    const float* beta  = (const float*)d_in[4];
    float* out = (float*)d_out;

    cudaFuncSetAttribute(gemm_tc, cudaFuncAttributeMaxDynamicSharedMemorySize, SM_DYN);

    dim3 cgrid(F_DIM / 32, T_DIM / 32, B_DIM);      // (32, 16, 64)
    convert_x<<<cgrid, dim3(32, 8)>>>(x);
    convert_w<<<T_DIM, 512>>>(W);
    stats_finalize<<<1, 512>>>(bias, gamma, beta);

    dim3 ggrid(F_DIM / GN, T_DIM / GM, B_DIM);      // (8, 4, 64)
    gemm_tc<<<ggrid, 512, SM_DYN>>>(x, out);
}